// round 4
// baseline (speedup 1.0000x reference)
#include <cuda_runtime.h>

#define BATCH 2
#define SEQ 2048
#define HID 2048
#define NH 32
#define NKV 8
#define HD 64
#define HALF 32
#define NREP 4

// ---------------- scratch (static device globals; no allocation) -------------
__device__ float g_qp[BATCH * SEQ * HID];        // x@wq   [4096, 2048]
__device__ float g_kp[BATCH * SEQ * NKV * HD];   // x@wk   [4096, 512]
__device__ float g_vp[BATCH * SEQ * NKV * HD];   // x@wv   [4096, 512]
__device__ float g_q[BATCH * NH * SEQ * HD];     // roped, scaled  [B,H,S,D]
__device__ float g_k[BATCH * NKV * SEQ * HD];    // roped          [B,KV,S,D]
__device__ float g_v[BATCH * NKV * SEQ * HD];    // transposed     [B,KV,S,D]
__device__ float g_ao[BATCH * SEQ * HID];        // attn out [B,S,H,D] = [4096,2048]

// ---------------- generic SGEMM: C[M,N] = A[M,K] @ B[K,N], row-major ---------
// 128x128 block tile, BK=8, 256 threads, 8x8 per-thread microtile.
__global__ __launch_bounds__(256)
void sgemm_kernel(const float* __restrict__ A, const float* __restrict__ Bm,
                  float* __restrict__ C, int M, int N, int K) {
    __shared__ float As[8][128];
    __shared__ float Bs[8][128];
    int tid = threadIdx.x;
    int bm = blockIdx.y * 128, bn = blockIdx.x * 128;

    int arow = tid >> 1, acol = (tid & 1) << 2;      // A: 128x8 tile, float4 per thread
    int brow = tid >> 5, bcol = (tid & 31) << 2;     // B: 8x128 tile, float4 per thread
    int tx = tid & 15, ty = tid >> 4;

    const float* Ap = A + (size_t)(bm + arow) * K + acol;
    const float* Bp = Bm + (size_t)brow * N + bn + bcol;

    float acc[8][8];
#pragma unroll
    for (int i = 0; i < 8; i++)
#pragma unroll
        for (int j = 0; j < 8; j++) acc[i][j] = 0.0f;

    for (int k0 = 0; k0 < K; k0 += 8) {
        float4 av = *(const float4*)Ap;
        float4 bv = *(const float4*)Bp;
        Ap += 8;
        Bp += (size_t)8 * N;
        __syncthreads();   // previous iteration's compute done
        As[acol + 0][arow] = av.x;
        As[acol + 1][arow] = av.y;
        As[acol + 2][arow] = av.z;
        As[acol + 3][arow] = av.w;
        *(float4*)&Bs[brow][bcol] = bv;
        __syncthreads();
#pragma unroll
        for (int kk = 0; kk < 8; kk++) {
            float4 a0 = *(const float4*)&As[kk][ty * 8];
            float4 a1 = *(const float4*)&As[kk][ty * 8 + 4];
            float4 b0 = *(const float4*)&Bs[kk][tx * 8];
            float4 b1 = *(const float4*)&Bs[kk][tx * 8 + 4];
            float ar[8] = {a0.x, a0.y, a0.z, a0.w, a1.x, a1.y, a1.z, a1.w};
            float br[8] = {b0.x, b0.y, b0.z, b0.w, b1.x, b1.y, b1.z, b1.w};
#pragma unroll
            for (int i = 0; i < 8; i++)
#pragma unroll
                for (int j = 0; j < 8; j++)
                    acc[i][j] = fmaf(ar[i], br[j], acc[i][j]);
        }
    }
#pragma unroll
    for (int i = 0; i < 8; i++) {
        float* Cp = C + (size_t)(bm + ty * 8 + i) * N + bn + tx * 8;
        *(float4*)Cp = make_float4(acc[i][0], acc[i][1], acc[i][2], acc[i][3]);
        *(float4*)(Cp + 4) = make_float4(acc[i][4], acc[i][5], acc[i][6], acc[i][7]);
    }
}

// ---------------- RoPE + layout transforms ----------------------------------
__global__ void rope_q_kernel(const float* __restrict__ qp, const float* __restrict__ fc,
                              const float* __restrict__ fs, float* __restrict__ Qo) {
    int idx = blockIdx.x * blockDim.x + threadIdx.x;
    if (idx >= BATCH * SEQ * NH * HALF) return;
    int p = idx & 31;
    int h = (idx >> 5) & 31;
    int s = (idx >> 10) & 2047;
    int b = idx >> 21;
    const float* src = qp + (size_t)(b * SEQ + s) * HID + h * HD + 2 * p;
    float tr = src[0], ti = src[1];
    float c = fc[s * HALF + p], sn = fs[s * HALF + p];
    float* dst = Qo + ((size_t)(b * NH + h) * SEQ + s) * HD + 2 * p;
    dst[0] = (tr * c - ti * sn) * 0.125f;   // fold 1/sqrt(64)
    dst[1] = (tr * sn + ti * c) * 0.125f;
}

__global__ void rope_k_kernel(const float* __restrict__ kp, const float* __restrict__ fc,
                              const float* __restrict__ fs, float* __restrict__ Ko) {
    int idx = blockIdx.x * blockDim.x + threadIdx.x;
    if (idx >= BATCH * SEQ * NKV * HALF) return;
    int p = idx & 31;
    int kvh = (idx >> 5) & 7;
    int s = (idx >> 8) & 2047;
    int b = idx >> 19;
    const float* src = kp + (size_t)(b * SEQ + s) * (NKV * HD) + kvh * HD + 2 * p;
    float tr = src[0], ti = src[1];
    float c = fc[s * HALF + p], sn = fs[s * HALF + p];
    float* dst = Ko + ((size_t)(b * NKV + kvh) * SEQ + s) * HD + 2 * p;
    dst[0] = tr * c - ti * sn;
    dst[1] = tr * sn + ti * c;
}

__global__ void copy_v_kernel(const float* __restrict__ vp, float* __restrict__ Vo) {
    int idx = blockIdx.x * blockDim.x + threadIdx.x;
    if (idx >= BATCH * SEQ * NKV * HD) return;
    int d = idx & 63;
    int kvh = (idx >> 6) & 7;
    int s = (idx >> 9) & 2047;
    int b = idx >> 20;
    Vo[((size_t)(b * NKV + kvh) * SEQ + s) * HD + d] =
        vp[(size_t)(b * SEQ + s) * (NKV * HD) + kvh * HD + d];
}

// ---------------- flash attention (fp32, causal, GQA) ------------------------
// Tile: 64 q-rows x 64 k-cols, D=64. 256 threads; thread (ty,tx) owns a 4x4
// microtile (rows ty*4.., cols tx*4..). smem pitch 68 floats (16B aligned).
#define APITCH 68
#define ATTN_SMEM (4 * 64 * APITCH * 4)

__global__ __launch_bounds__(256)
void attn_kernel(const float* __restrict__ Q, const float* __restrict__ K,
                 const float* __restrict__ V, float* __restrict__ O) {
    extern __shared__ float sm[];
    float* QsT = sm;                   // [d][r]  transposed
    float* KsT = sm + 64 * APITCH;     // [d][c]  transposed
    float* Vs  = sm + 2 * 64 * APITCH; // [kn][d]
    float* PsT = sm + 3 * 64 * APITCH; // [kn][r] transposed

    int tid = threadIdx.x;
    int qt = blockIdx.x;
    int bh = blockIdx.y;
    int b = bh >> 5, h = bh & 31;
    int kvh = h >> 2;
    int q0 = qt * 64;

    const float* Qbase = Q + ((size_t)(b * NH + h) * SEQ + q0) * HD;
    const float* Kbase = K + (size_t)(b * NKV + kvh) * SEQ * HD;
    const float* Vbase = V + (size_t)(b * NKV + kvh) * SEQ * HD;

    // load + transpose Q tile
#pragma unroll
    for (int p = 0; p < 4; p++) {
        int idx = p * 256 + tid;
        int row = idx >> 4, c4 = (idx & 15) << 2;
        float4 qv = *(const float4*)(Qbase + row * HD + c4);
        QsT[(c4 + 0) * APITCH + row] = qv.x;
        QsT[(c4 + 1) * APITCH + row] = qv.y;
        QsT[(c4 + 2) * APITCH + row] = qv.z;
        QsT[(c4 + 3) * APITCH + row] = qv.w;
    }

    int tx = tid & 15, ty = tid >> 4;
    float m_i[4], l_i[4], acc[4][4];
#pragma unroll
    for (int i = 0; i < 4; i++) {
        m_i[i] = -1e30f;
        l_i[i] = 0.0f;
#pragma unroll
        for (int j = 0; j < 4; j++) acc[i][j] = 0.0f;
    }
    __syncthreads();

    for (int kt = 0; kt <= qt; kt++) {
        const float* Kp = Kbase + (size_t)kt * 64 * HD;
        const float* Vp = Vbase + (size_t)kt * 64 * HD;
#pragma unroll
        for (int p = 0; p < 4; p++) {
            int idx = p * 256 + tid;
            int row = idx >> 4, c4 = (idx & 15) << 2;
            float4 kv = *(const float4*)(Kp + row * HD + c4);
            KsT[(c4 + 0) * APITCH + row] = kv.x;
            KsT[(c4 + 1) * APITCH + row] = kv.y;
            KsT[(c4 + 2) * APITCH + row] = kv.z;
            KsT[(c4 + 3) * APITCH + row] = kv.w;
            float4 vv = *(const float4*)(Vp + row * HD + c4);
            *(float4*)&Vs[row * APITCH + c4] = vv;
        }
        __syncthreads();

        // S = Q @ K^T (Q already scaled)
        float s[4][4];
#pragma unroll
        for (int i = 0; i < 4; i++)
#pragma unroll
            for (int j = 0; j < 4; j++) s[i][j] = 0.0f;
#pragma unroll 8
        for (int d = 0; d < 64; d++) {
            float ar[4];
#pragma unroll
            for (int i = 0; i < 4; i++) ar[i] = QsT[d * APITCH + ty * 4 + i];
            float4 bb = *(const float4*)&KsT[d * APITCH + tx * 4];
            float br[4] = {bb.x, bb.y, bb.z, bb.w};
#pragma unroll
            for (int i = 0; i < 4; i++)
#pragma unroll
                for (int j = 0; j < 4; j++)
                    s[i][j] = fmaf(ar[i], br[j], s[i][j]);
        }

        if (kt == qt) {  // diagonal tile: causal mask (col > row)
#pragma unroll
            for (int i = 0; i < 4; i++)
#pragma unroll
                for (int j = 0; j < 4; j++)
                    if (tx * 4 + j > ty * 4 + i) s[i][j] = -1e30f;
        }

        // online softmax per row; row spans 16 lanes (same ty)
#pragma unroll
        for (int i = 0; i < 4; i++) {
            float mx = fmaxf(fmaxf(s[i][0], s[i][1]), fmaxf(s[i][2], s[i][3]));
#pragma unroll
            for (int off = 8; off >= 1; off >>= 1)
                mx = fmaxf(mx, __shfl_xor_sync(0xffffffffu, mx, off));
            float mn = fmaxf(m_i[i], mx);
            float scale = __expf(m_i[i] - mn);
            m_i[i] = mn;
            float sum = 0.0f;
#pragma unroll
            for (int j = 0; j < 4; j++) {
                s[i][j] = __expf(s[i][j] - mn);
                sum += s[i][j];
            }
#pragma unroll
            for (int off = 8; off >= 1; off >>= 1)
                sum += __shfl_xor_sync(0xffffffffu, sum, off);
            l_i[i] = l_i[i] * scale + sum;
#pragma unroll
            for (int j = 0; j < 4; j++) acc[i][j] *= scale;
        }

        // stage P transposed
#pragma unroll
        for (int i = 0; i < 4; i++)
#pragma unroll
            for (int j = 0; j < 4; j++)
                PsT[(tx * 4 + j) * APITCH + ty * 4 + i] = s[i][j];
        __syncthreads();

        // O += P @ V
#pragma unroll 8
        for (int kk = 0; kk < 64; kk++) {
            float ar[4];
#pragma unroll
            for (int i = 0; i < 4; i++) ar[i] = PsT[kk * APITCH + ty * 4 + i];
            float4 bb = *(const float4*)&Vs[kk * APITCH + tx * 4];
            float br[4] = {bb.x, bb.y, bb.z, bb.w};
#pragma unroll
            for (int i = 0; i < 4; i++)
#pragma unroll
                for (int j = 0; j < 4; j++)
                    acc[i][j] = fmaf(ar[i], br[j], acc[i][j]);
        }
        __syncthreads();
    }

    // normalize + write [B,S,H,D]
#pragma unroll
    for (int i = 0; i < 4; i++) {
        float rl = 1.0f / l_i[i];
        int r = q0 + ty * 4 + i;
        float4 o = make_float4(acc[i][0] * rl, acc[i][1] * rl,
                               acc[i][2] * rl, acc[i][3] * rl);
        *(float4*)(O + ((size_t)(b * SEQ + r) * NH + h) * HD + tx * 4) = o;
    }
}

// ---------------- launcher ---------------------------------------------------
extern "C" void kernel_launch(void* const* d_in, const int* in_sizes, int n_in,
                              void* d_out, int out_size) {
    const float* x  = (const float*)d_in[0];
    const float* wq = (const float*)d_in[1];
    const float* wk = (const float*)d_in[2];
    const float* wv = (const float*)d_in[3];
    const float* wo = (const float*)d_in[4];
    const float* fc = (const float*)d_in[5];
    const float* fs = (const float*)d_in[6];
    float* out = (float*)d_out;

    float *qp, *kp, *vp, *q, *k, *v, *ao;
    cudaGetSymbolAddress((void**)&qp, g_qp);
    cudaGetSymbolAddress((void**)&kp, g_kp);
    cudaGetSymbolAddress((void**)&vp, g_vp);
    cudaGetSymbolAddress((void**)&q,  g_q);
    cudaGetSymbolAddress((void**)&k,  g_k);
    cudaGetSymbolAddress((void**)&v,  g_v);
    cudaGetSymbolAddress((void**)&ao, g_ao);

    const int M = BATCH * SEQ;  // 4096

    // QKV projections
    sgemm_kernel<<<dim3(HID / 128, M / 128), 256>>>(x, wq, qp, M, HID, HID);
    sgemm_kernel<<<dim3((NKV * HD) / 128, M / 128), 256>>>(x, wk, kp, M, NKV * HD, HID);
    sgemm_kernel<<<dim3((NKV * HD) / 128, M / 128), 256>>>(x, wv, vp, M, NKV * HD, HID);

    // RoPE + layout
    rope_q_kernel<<<(BATCH * SEQ * NH * HALF) / 256, 256>>>(qp, fc, fs, q);
    rope_k_kernel<<<(BATCH * SEQ * NKV * HALF) / 256, 256>>>(kp, fc, fs, k);
    copy_v_kernel<<<(BATCH * SEQ * NKV * HD) / 256, 256>>>(vp, v);

    // flash attention
    cudaFuncSetAttribute(attn_kernel, cudaFuncAttributeMaxDynamicSharedMemorySize,
                         ATTN_SMEM);
    attn_kernel<<<dim3(SEQ / 64, BATCH * NH), 256, ATTN_SMEM>>>(q, k, v, ao);

    // output projection
    sgemm_kernel<<<dim3(HID / 128, M / 128), 256>>>(ao, wo, out, M, HID, HID);
}

// round 6
// speedup vs baseline: 3.0544x; 3.0544x over previous
#include <cuda_runtime.h>
#include <cstdint>

#define BATCH 2
#define SEQ 2048
#define HID 2048
#define NH 32
#define NKV 8
#define HD 64
#define HALF 32
#define NREP 4
#define GK 2048          // reduction dim for all projection GEMMs
#define CHUNK 32
#define NCHUNK (GK / CHUNK)

// ---------------- scratch (static device globals; no allocation) -------------
__device__ float g_qp[BATCH * SEQ * HID];        // x@wq   [4096, 2048]
__device__ float g_kp[BATCH * SEQ * NKV * HD];   // x@wk   [4096, 512]
__device__ float g_vp[BATCH * SEQ * NKV * HD];   // x@wv   [4096, 512]
__device__ float g_q[BATCH * NH * SEQ * HD];     // roped, scaled  [B,H,S,D]
__device__ float g_k[BATCH * NKV * SEQ * HD];    // roped          [B,KV,S,D]
__device__ float g_v[BATCH * NKV * SEQ * HD];    // transposed     [B,KV,S,D]
__device__ float g_ao[BATCH * SEQ * HID];        // attn out [B,S,H,D]
__device__ float g_wqT[HID * HID];               // wq^T [2048,2048]
__device__ float g_wkT[NKV * HD * HID];          // wk^T [512,2048]
__device__ float g_wvT[NKV * HD * HID];          // wv^T [512,2048]
__device__ float g_woT[HID * HID];               // wo^T [2048,2048]

// ---------------- helpers ----------------------------------------------------
__device__ __forceinline__ uint32_t f2tf(float x) {
    uint32_t r;
    asm("cvt.rna.tf32.f32 %0, %1;" : "=r"(r) : "f"(x));
    return r;
}

#define MMA_TF32(d, a, b)                                                      \
    asm volatile("mma.sync.aligned.m16n8k8.row.col.f32.tf32.tf32.f32 "         \
        "{%0,%1,%2,%3}, {%4,%5,%6,%7}, {%8,%9}, {%0,%1,%2,%3};"                \
        : "+f"((d)[0]), "+f"((d)[1]), "+f"((d)[2]), "+f"((d)[3])               \
        : "r"((a)[0]), "r"((a)[1]), "r"((a)[2]), "r"((a)[3]),                  \
          "r"((b)[0]), "r"((b)[1]))

// ---------------- weight transpose: out[C][R] = in[R][C] ---------------------
__global__ void transpose_kernel(const float* __restrict__ in, float* __restrict__ out,
                                 int R, int C) {
    __shared__ float t[32][33];
    int bx = blockIdx.x * 32, by = blockIdx.y * 32;
#pragma unroll
    for (int j = 0; j < 32; j += 8)
        t[threadIdx.y + j][threadIdx.x] =
            in[(size_t)(by + threadIdx.y + j) * C + bx + threadIdx.x];
    __syncthreads();
#pragma unroll
    for (int j = 0; j < 32; j += 8)
        out[(size_t)(bx + threadIdx.y + j) * R + by + threadIdx.x] =
            t[threadIdx.x][threadIdx.y + j];
}

// ---------------- TF32 mma.sync GEMM -----------------------------------------
// C[M,N] = A[M,GK] @ BT[N,GK]^T, both operands K-major.
// CTA: 128x128 tile, 256 threads = 8 warps (2 M x 4 N), warp tile 64x32.
// Smem: padded pitch 36 floats; chunk = 32 k; double-buffered.
#define APAD 36
#define TILE_F (128 * APAD)                  // floats per tile
#define BUF_BYTES (2 * TILE_F * 4)           // A+B one buffer
#define GEMM_SMEM (2 * BUF_BYTES)            // double buffered (73728 B)

__global__ __launch_bounds__(256)
void tf32_gemm(const float* __restrict__ A, const float* __restrict__ BT,
               float* __restrict__ C, int N) {
    extern __shared__ uint32_t smem[];
    int tid = threadIdx.x;
    int w = tid >> 5, lane = tid & 31;
    int g = lane >> 2, t = lane & 3;
    int wm = (w >> 2) * 64;            // warp M origin (0 or 64)
    int wn = (w & 3) * 32;             // warp N origin
    int bm = blockIdx.y * 128, bn = blockIdx.x * 128;

    const float* Ab = A + (size_t)bm * GK;
    const float* Bb = BT + (size_t)bn * GK;

    int lrow = tid >> 3;               // 0..31 per 256-thread pass -> 4 passes = 128 rows
    int lc4 = (tid & 7) << 2;          // k-offset within chunk

    float acc[4][4][4];
#pragma unroll
    for (int mi = 0; mi < 4; mi++)
#pragma unroll
        for (int ni = 0; ni < 4; ni++)
#pragma unroll
            for (int e = 0; e < 4; e++) acc[mi][ni][e] = 0.0f;

    float4 av[4], bv[4];
    // ---- prefetch + store chunk 0 ----
#pragma unroll
    for (int p = 0; p < 4; p++) {
        int row = p * 32 + lrow;
        av[p] = *(const float4*)(Ab + (size_t)row * GK + lc4);
        bv[p] = *(const float4*)(Bb + (size_t)row * GK + lc4);
    }
    {
        uint32_t* As = smem;
        uint32_t* Bs = smem + TILE_F;
#pragma unroll
        for (int p = 0; p < 4; p++) {
            int row = p * 32 + lrow;
            uint32_t* ap = As + row * APAD + lc4;
            ap[0] = f2tf(av[p].x); ap[1] = f2tf(av[p].y);
            ap[2] = f2tf(av[p].z); ap[3] = f2tf(av[p].w);
            uint32_t* bp = Bs + row * APAD + lc4;
            bp[0] = f2tf(bv[p].x); bp[1] = f2tf(bv[p].y);
            bp[2] = f2tf(bv[p].z); bp[3] = f2tf(bv[p].w);
        }
    }
    __syncthreads();

    for (int i = 0; i < NCHUNK; i++) {
        if (i + 1 < NCHUNK) {
            int k0 = (i + 1) * CHUNK;
#pragma unroll
            for (int p = 0; p < 4; p++) {
                int row = p * 32 + lrow;
                av[p] = *(const float4*)(Ab + (size_t)row * GK + k0 + lc4);
                bv[p] = *(const float4*)(Bb + (size_t)row * GK + k0 + lc4);
            }
        }
        // ---- compute on buffer i&1 ----
        {
            uint32_t* As = smem + (i & 1) * 2 * TILE_F;
            uint32_t* Bs = As + TILE_F;
#pragma unroll
            for (int ks = 0; ks < 4; ks++) {
                int kk = ks * 8;
                uint32_t afr[4][4];
#pragma unroll
                for (int mi = 0; mi < 4; mi++) {
                    int r0 = wm + mi * 16 + g;
                    afr[mi][0] = As[r0 * APAD + kk + t];
                    afr[mi][1] = As[(r0 + 8) * APAD + kk + t];
                    afr[mi][2] = As[r0 * APAD + kk + t + 4];
                    afr[mi][3] = As[(r0 + 8) * APAD + kk + t + 4];
                }
                uint32_t bfr[4][2];
#pragma unroll
                for (int ni = 0; ni < 4; ni++) {
                    int n0 = wn + ni * 8 + g;
                    bfr[ni][0] = Bs[n0 * APAD + kk + t];
                    bfr[ni][1] = Bs[n0 * APAD + kk + t + 4];
                }
#pragma unroll
                for (int mi = 0; mi < 4; mi++)
#pragma unroll
                    for (int ni = 0; ni < 4; ni++)
                        MMA_TF32(acc[mi][ni], afr[mi], bfr[ni]);
            }
        }
        // ---- store next chunk ----
        if (i + 1 < NCHUNK) {
            __syncthreads();
            uint32_t* As = smem + ((i + 1) & 1) * 2 * TILE_F;
            uint32_t* Bs = As + TILE_F;
#pragma unroll
            for (int p = 0; p < 4; p++) {
                int row = p * 32 + lrow;
                uint32_t* ap = As + row * APAD + lc4;
                ap[0] = f2tf(av[p].x); ap[1] = f2tf(av[p].y);
                ap[2] = f2tf(av[p].z); ap[3] = f2tf(av[p].w);
                uint32_t* bp = Bs + row * APAD + lc4;
                bp[0] = f2tf(bv[p].x); bp[1] = f2tf(bv[p].y);
                bp[2] = f2tf(bv[p].z); bp[3] = f2tf(bv[p].w);
            }
            __syncthreads();
        }
    }

    // ---- epilogue ----
#pragma unroll
    for (int mi = 0; mi < 4; mi++) {
#pragma unroll
        for (int ni = 0; ni < 4; ni++) {
            int r0 = bm + wm + mi * 16 + g;
            int c0 = bn + wn + ni * 8 + t * 2;
            *(float2*)(C + (size_t)r0 * N + c0) =
                make_float2(acc[mi][ni][0], acc[mi][ni][1]);
            *(float2*)(C + (size_t)(r0 + 8) * N + c0) =
                make_float2(acc[mi][ni][2], acc[mi][ni][3]);
        }
    }
}

// ---------------- RoPE + layout transforms ----------------------------------
__global__ void rope_q_kernel(const float* __restrict__ qp, const float* __restrict__ fc,
                              const float* __restrict__ fs, float* __restrict__ Qo) {
    int idx = blockIdx.x * blockDim.x + threadIdx.x;
    if (idx >= BATCH * SEQ * NH * HALF) return;
    int p = idx & 31;
    int h = (idx >> 5) & 31;
    int s = (idx >> 10) & 2047;
    int b = idx >> 21;
    const float* src = qp + (size_t)(b * SEQ + s) * HID + h * HD + 2 * p;
    float tr = src[0], ti = src[1];
    float c = fc[s * HALF + p], sn = fs[s * HALF + p];
    float* dst = Qo + ((size_t)(b * NH + h) * SEQ + s) * HD + 2 * p;
    dst[0] = (tr * c - ti * sn) * 0.125f;   // fold 1/sqrt(64)
    dst[1] = (tr * sn + ti * c) * 0.125f;
}

__global__ void rope_k_kernel(const float* __restrict__ kp, const float* __restrict__ fc,
                              const float* __restrict__ fs, float* __restrict__ Ko) {
    int idx = blockIdx.x * blockDim.x + threadIdx.x;
    if (idx >= BATCH * SEQ * NKV * HALF) return;
    int p = idx & 31;
    int kvh = (idx >> 5) & 7;
    int s = (idx >> 8) & 2047;
    int b = idx >> 19;
    const float* src = kp + (size_t)(b * SEQ + s) * (NKV * HD) + kvh * HD + 2 * p;
    float tr = src[0], ti = src[1];
    float c = fc[s * HALF + p], sn = fs[s * HALF + p];
    float* dst = Ko + ((size_t)(b * NKV + kvh) * SEQ + s) * HD + 2 * p;
    dst[0] = tr * c - ti * sn;
    dst[1] = tr * sn + ti * c;
}

__global__ void copy_v_kernel(const float* __restrict__ vp, float* __restrict__ Vo) {
    int idx = blockIdx.x * blockDim.x + threadIdx.x;
    if (idx >= BATCH * SEQ * NKV * HD) return;
    int d = idx & 63;
    int kvh = (idx >> 6) & 7;
    int s = (idx >> 9) & 2047;
    int b = idx >> 20;
    Vo[((size_t)(b * NKV + kvh) * SEQ + s) * HD + d] =
        vp[(size_t)(b * SEQ + s) * (NKV * HD) + kvh * HD + d];
}

// ---------------- flash attention (fp32, causal, GQA) ------------------------
#define APITCH 68
#define ATTN_SMEM (4 * 64 * APITCH * 4)

__global__ __launch_bounds__(256)
void attn_kernel(const float* __restrict__ Q, const float* __restrict__ K,
                 const float* __restrict__ V, float* __restrict__ O) {
    extern __shared__ float sm[];
    float* QsT = sm;                   // [d][r]  transposed
    float* KsT = sm + 64 * APITCH;     // [d][c]  transposed
    float* Vs  = sm + 2 * 64 * APITCH; // [kn][d]
    float* PsT = sm + 3 * 64 * APITCH; // [kn][r] transposed

    int tid = threadIdx.x;
    int qt = blockIdx.x;
    int bh = blockIdx.y;
    int b = bh >> 5, h = bh & 31;
    int kvh = h >> 2;
    int q0 = qt * 64;

    const float* Qbase = Q + ((size_t)(b * NH + h) * SEQ + q0) * HD;
    const float* Kbase = K + (size_t)(b * NKV + kvh) * SEQ * HD;
    const float* Vbase = V + (size_t)(b * NKV + kvh) * SEQ * HD;

#pragma unroll
    for (int p = 0; p < 4; p++) {
        int idx = p * 256 + tid;
        int row = idx >> 4, c4 = (idx & 15) << 2;
        float4 qv = *(const float4*)(Qbase + row * HD + c4);
        QsT[(c4 + 0) * APITCH + row] = qv.x;
        QsT[(c4 + 1) * APITCH + row] = qv.y;
        QsT[(c4 + 2) * APITCH + row] = qv.z;
        QsT[(c4 + 3) * APITCH + row] = qv.w;
    }

    int tx = tid & 15, ty = tid >> 4;
    float m_i[4], l_i[4], acc[4][4];
#pragma unroll
    for (int i = 0; i < 4; i++) {
        m_i[i] = -1e30f;
        l_i[i] = 0.0f;
#pragma unroll
        for (int j = 0; j < 4; j++) acc[i][j] = 0.0f;
    }
    __syncthreads();

    for (int kt = 0; kt <= qt; kt++) {
        const float* Kp = Kbase + (size_t)kt * 64 * HD;
        const float* Vp = Vbase + (size_t)kt * 64 * HD;
#pragma unroll
        for (int p = 0; p < 4; p++) {
            int idx = p * 256 + tid;
            int row = idx >> 4, c4 = (idx & 15) << 2;
            float4 kv = *(const float4*)(Kp + row * HD + c4);
            KsT[(c4 + 0) * APITCH + row] = kv.x;
            KsT[(c4 + 1) * APITCH + row] = kv.y;
            KsT[(c4 + 2) * APITCH + row] = kv.z;
            KsT[(c4 + 3) * APITCH + row] = kv.w;
            float4 vv = *(const float4*)(Vp + row * HD + c4);
            *(float4*)&Vs[row * APITCH + c4] = vv;
        }
        __syncthreads();

        float s[4][4];
#pragma unroll
        for (int i = 0; i < 4; i++)
#pragma unroll
            for (int j = 0; j < 4; j++) s[i][j] = 0.0f;
#pragma unroll 8
        for (int d = 0; d < 64; d++) {
            float ar[4];
#pragma unroll
            for (int i = 0; i < 4; i++) ar[i] = QsT[d * APITCH + ty * 4 + i];
            float4 bb = *(const float4*)&KsT[d * APITCH + tx * 4];
            float br[4] = {bb.x, bb.y, bb.z, bb.w};
#pragma unroll
            for (int i = 0; i < 4; i++)
#pragma unroll
                for (int j = 0; j < 4; j++)
                    s[i][j] = fmaf(ar[i], br[j], s[i][j]);
        }

        if (kt == qt) {
#pragma unroll
            for (int i = 0; i < 4; i++)
#pragma unroll
                for (int j = 0; j < 4; j++)
                    if (tx * 4 + j > ty * 4 + i) s[i][j] = -1e30f;
        }

#pragma unroll
        for (int i = 0; i < 4; i++) {
            float mx = fmaxf(fmaxf(s[i][0], s[i][1]), fmaxf(s[i][2], s[i][3]));
#pragma unroll
            for (int off = 8; off >= 1; off >>= 1)
                mx = fmaxf(mx, __shfl_xor_sync(0xffffffffu, mx, off));
            float mn = fmaxf(m_i[i], mx);
            float scale = __expf(m_i[i] - mn);
            m_i[i] = mn;
            float sum = 0.0f;
#pragma unroll
            for (int j = 0; j < 4; j++) {
                s[i][j] = __expf(s[i][j] - mn);
                sum += s[i][j];
            }
#pragma unroll
            for (int off = 8; off >= 1; off >>= 1)
                sum += __shfl_xor_sync(0xffffffffu, sum, off);
            l_i[i] = l_i[i] * scale + sum;
#pragma unroll
            for (int j = 0; j < 4; j++) acc[i][j] *= scale;
        }

#pragma unroll
        for (int i = 0; i < 4; i++)
#pragma unroll
            for (int j = 0; j < 4; j++)
                PsT[(tx * 4 + j) * APITCH + ty * 4 + i] = s[i][j];
        __syncthreads();

#pragma unroll 8
        for (int kk = 0; kk < 64; kk++) {
            float ar[4];
#pragma unroll
            for (int i = 0; i < 4; i++) ar[i] = PsT[kk * APITCH + ty * 4 + i];
            float4 bb = *(const float4*)&Vs[kk * APITCH + tx * 4];
            float br[4] = {bb.x, bb.y, bb.z, bb.w};
#pragma unroll
            for (int i = 0; i < 4; i++)
#pragma unroll
                for (int j = 0; j < 4; j++)
                    acc[i][j] = fmaf(ar[i], br[j], acc[i][j]);
        }
        __syncthreads();
    }

#pragma unroll
    for (int i = 0; i < 4; i++) {
        float rl = 1.0f / l_i[i];
        int r = q0 + ty * 4 + i;
        float4 o = make_float4(acc[i][0] * rl, acc[i][1] * rl,
                               acc[i][2] * rl, acc[i][3] * rl);
        *(float4*)(O + ((size_t)(b * SEQ + r) * NH + h) * HD + tx * 4) = o;
    }
}

// ---------------- launcher ---------------------------------------------------
extern "C" void kernel_launch(void* const* d_in, const int* in_sizes, int n_in,
                              void* d_out, int out_size) {
    const float* x  = (const float*)d_in[0];
    const float* wq = (const float*)d_in[1];
    const float* wk = (const float*)d_in[2];
    const float* wv = (const float*)d_in[3];
    const float* wo = (const float*)d_in[4];
    const float* fc = (const float*)d_in[5];
    const float* fs = (const float*)d_in[6];
    float* out = (float*)d_out;

    float *qp, *kp, *vp, *q, *k, *v, *ao, *wqT, *wkT, *wvT, *woT;
    cudaGetSymbolAddress((void**)&qp, g_qp);
    cudaGetSymbolAddress((void**)&kp, g_kp);
    cudaGetSymbolAddress((void**)&vp, g_vp);
    cudaGetSymbolAddress((void**)&q,  g_q);
    cudaGetSymbolAddress((void**)&k,  g_k);
    cudaGetSymbolAddress((void**)&v,  g_v);
    cudaGetSymbolAddress((void**)&ao, g_ao);
    cudaGetSymbolAddress((void**)&wqT, g_wqT);
    cudaGetSymbolAddress((void**)&wkT, g_wkT);
    cudaGetSymbolAddress((void**)&wvT, g_wvT);
    cudaGetSymbolAddress((void**)&woT, g_woT);

    const int M = BATCH * SEQ;  // 4096

    // transpose weights to [N, K] so GEMM B-tiles load K-major coalesced
    transpose_kernel<<<dim3(HID / 32, HID / 32), dim3(32, 8)>>>(wq, wqT, HID, HID);
    transpose_kernel<<<dim3((NKV * HD) / 32, HID / 32), dim3(32, 8)>>>(wk, wkT, HID, NKV * HD);
    transpose_kernel<<<dim3((NKV * HD) / 32, HID / 32), dim3(32, 8)>>>(wv, wvT, HID, NKV * HD);
    transpose_kernel<<<dim3(HID / 32, HID / 32), dim3(32, 8)>>>(wo, woT, HID, HID);

    cudaFuncSetAttribute(tf32_gemm, cudaFuncAttributeMaxDynamicSharedMemorySize,
                         GEMM_SMEM);

    // QKV projections (mma.sync tf32)
    tf32_gemm<<<dim3(HID / 128, M / 128), 256, GEMM_SMEM>>>(x, wqT, qp, HID);
    tf32_gemm<<<dim3((NKV * HD) / 128, M / 128), 256, GEMM_SMEM>>>(x, wkT, kp, NKV * HD);
    tf32_gemm<<<dim3((NKV * HD) / 128, M / 128), 256, GEMM_SMEM>>>(x, wvT, vp, NKV * HD);

    // RoPE + layout
    rope_q_kernel<<<(BATCH * SEQ * NH * HALF) / 256, 256>>>(qp, fc, fs, q);
    rope_k_kernel<<<(BATCH * SEQ * NKV * HALF) / 256, 256>>>(kp, fc, fs, k);
    copy_v_kernel<<<(BATCH * SEQ * NKV * HD) / 256, 256>>>(vp, v);

    // flash attention (fp32)
    cudaFuncSetAttribute(attn_kernel, cudaFuncAttributeMaxDynamicSharedMemorySize,
                         ATTN_SMEM);
    attn_kernel<<<dim3(SEQ / 64, BATCH * NH), 256, ATTN_SMEM>>>(q, k, v, ao);

    // output projection (mma.sync tf32)
    tf32_gemm<<<dim3(HID / 128, M / 128), 256, GEMM_SMEM>>>(ao, woT, out, HID);
}

// round 8
// speedup vs baseline: 5.4909x; 1.7977x over previous
#include <cuda_runtime.h>
#include <cstdint>

#define BATCH 2
#define SEQ 2048
#define HID 2048
#define NH 32
#define NKV 8
#define HD 64
#define HALF 32
#define NREP 4
#define GK 2048          // reduction dim for all projection GEMMs
#define CHUNK 32
#define NCHUNK (GK / CHUNK)

// ---------------- scratch (static device globals; no allocation) -------------
__device__ float g_qp[BATCH * SEQ * HID];        // x@wq   [4096, 2048]
__device__ float g_kp[BATCH * SEQ * NKV * HD];   // x@wk   [4096, 512]
__device__ float g_vp[BATCH * SEQ * NKV * HD];   // x@wv   [4096, 512]
__device__ float g_q[BATCH * NH * SEQ * HD];     // roped, scaled  [B,H,S,D]
__device__ float g_k[BATCH * NKV * SEQ * HD];    // roped          [B,KV,S,D]
__device__ float g_v[BATCH * NKV * SEQ * HD];    // transposed     [B,KV,S,D]
__device__ float g_ao[BATCH * SEQ * HID];        // attn out [B,S,H,D]
__device__ float g_wqT[HID * HID];               // wq^T [2048,2048]
__device__ float g_wkT[NKV * HD * HID];          // wk^T [512,2048]
__device__ float g_wvT[NKV * HD * HID];          // wv^T [512,2048]
__device__ float g_woT[HID * HID];               // wo^T [2048,2048]

// ---------------- helpers ----------------------------------------------------
__device__ __forceinline__ uint32_t f2tf(float x) {
    uint32_t r;
    asm("cvt.rna.tf32.f32 %0, %1;" : "=r"(r) : "f"(x));
    return r;
}

#define MMA_TF32(d, a, b)                                                      \
    asm volatile("mma.sync.aligned.m16n8k8.row.col.f32.tf32.tf32.f32 "         \
        "{%0,%1,%2,%3}, {%4,%5,%6,%7}, {%8,%9}, {%0,%1,%2,%3};"                \
        : "+f"((d)[0]), "+f"((d)[1]), "+f"((d)[2]), "+f"((d)[3])               \
        : "r"((a)[0]), "r"((a)[1]), "r"((a)[2]), "r"((a)[3]),                  \
          "r"((b)[0]), "r"((b)[1]))

// ---------------- weight transpose: out[C][R] = in[R][C] ---------------------
__global__ void transpose_kernel(const float* __restrict__ in, float* __restrict__ out,
                                 int R, int C) {
    __shared__ float t[32][33];
    int bx = blockIdx.x * 32, by = blockIdx.y * 32;
#pragma unroll
    for (int j = 0; j < 32; j += 8)
        t[threadIdx.y + j][threadIdx.x] =
            in[(size_t)(by + threadIdx.y + j) * C + bx + threadIdx.x];
    __syncthreads();
#pragma unroll
    for (int j = 0; j < 32; j += 8)
        out[(size_t)(bx + threadIdx.y + j) * R + by + threadIdx.x] =
            t[threadIdx.x][threadIdx.y + j];
}

// ---------------- TF32 mma.sync GEMM -----------------------------------------
// C[M,N] = A[M,GK] @ BT[N,GK]^T, both operands K-major.
#define APAD 36
#define TILE_F (128 * APAD)
#define BUF_BYTES (2 * TILE_F * 4)
#define GEMM_SMEM (2 * BUF_BYTES)

__global__ __launch_bounds__(256)
void tf32_gemm(const float* __restrict__ A, const float* __restrict__ BT,
               float* __restrict__ C, int N) {
    extern __shared__ uint32_t smem[];
    int tid = threadIdx.x;
    int w = tid >> 5, lane = tid & 31;
    int g = lane >> 2, t = lane & 3;
    int wm = (w >> 2) * 64;
    int wn = (w & 3) * 32;
    int bm = blockIdx.y * 128, bn = blockIdx.x * 128;

    const float* Ab = A + (size_t)bm * GK;
    const float* Bb = BT + (size_t)bn * GK;

    int lrow = tid >> 3;
    int lc4 = (tid & 7) << 2;

    float acc[4][4][4];
#pragma unroll
    for (int mi = 0; mi < 4; mi++)
#pragma unroll
        for (int ni = 0; ni < 4; ni++)
#pragma unroll
            for (int e = 0; e < 4; e++) acc[mi][ni][e] = 0.0f;

    float4 av[4], bv[4];
#pragma unroll
    for (int p = 0; p < 4; p++) {
        int row = p * 32 + lrow;
        av[p] = *(const float4*)(Ab + (size_t)row * GK + lc4);
        bv[p] = *(const float4*)(Bb + (size_t)row * GK + lc4);
    }
    {
        uint32_t* As = smem;
        uint32_t* Bs = smem + TILE_F;
#pragma unroll
        for (int p = 0; p < 4; p++) {
            int row = p * 32 + lrow;
            uint32_t* ap = As + row * APAD + lc4;
            ap[0] = f2tf(av[p].x); ap[1] = f2tf(av[p].y);
            ap[2] = f2tf(av[p].z); ap[3] = f2tf(av[p].w);
            uint32_t* bp = Bs + row * APAD + lc4;
            bp[0] = f2tf(bv[p].x); bp[1] = f2tf(bv[p].y);
            bp[2] = f2tf(bv[p].z); bp[3] = f2tf(bv[p].w);
        }
    }
    __syncthreads();

    for (int i = 0; i < NCHUNK; i++) {
        if (i + 1 < NCHUNK) {
            int k0 = (i + 1) * CHUNK;
#pragma unroll
            for (int p = 0; p < 4; p++) {
                int row = p * 32 + lrow;
                av[p] = *(const float4*)(Ab + (size_t)row * GK + k0 + lc4);
                bv[p] = *(const float4*)(Bb + (size_t)row * GK + k0 + lc4);
            }
        }
        {
            uint32_t* As = smem + (i & 1) * 2 * TILE_F;
            uint32_t* Bs = As + TILE_F;
#pragma unroll
            for (int ks = 0; ks < 4; ks++) {
                int kk = ks * 8;
                uint32_t afr[4][4];
#pragma unroll
                for (int mi = 0; mi < 4; mi++) {
                    int r0 = wm + mi * 16 + g;
                    afr[mi][0] = As[r0 * APAD + kk + t];
                    afr[mi][1] = As[(r0 + 8) * APAD + kk + t];
                    afr[mi][2] = As[r0 * APAD + kk + t + 4];
                    afr[mi][3] = As[(r0 + 8) * APAD + kk + t + 4];
                }
                uint32_t bfr[4][2];
#pragma unroll
                for (int ni = 0; ni < 4; ni++) {
                    int n0 = wn + ni * 8 + g;
                    bfr[ni][0] = Bs[n0 * APAD + kk + t];
                    bfr[ni][1] = Bs[n0 * APAD + kk + t + 4];
                }
#pragma unroll
                for (int mi = 0; mi < 4; mi++)
#pragma unroll
                    for (int ni = 0; ni < 4; ni++)
                        MMA_TF32(acc[mi][ni], afr[mi], bfr[ni]);
            }
        }
        if (i + 1 < NCHUNK) {
            __syncthreads();
            uint32_t* As = smem + ((i + 1) & 1) * 2 * TILE_F;
            uint32_t* Bs = As + TILE_F;
#pragma unroll
            for (int p = 0; p < 4; p++) {
                int row = p * 32 + lrow;
                uint32_t* ap = As + row * APAD + lc4;
                ap[0] = f2tf(av[p].x); ap[1] = f2tf(av[p].y);
                ap[2] = f2tf(av[p].z); ap[3] = f2tf(av[p].w);
                uint32_t* bp = Bs + row * APAD + lc4;
                bp[0] = f2tf(bv[p].x); bp[1] = f2tf(bv[p].y);
                bp[2] = f2tf(bv[p].z); bp[3] = f2tf(bv[p].w);
            }
            __syncthreads();
        }
    }

#pragma unroll
    for (int mi = 0; mi < 4; mi++) {
#pragma unroll
        for (int ni = 0; ni < 4; ni++) {
            int r0 = bm + wm + mi * 16 + g;
            int c0 = bn + wn + ni * 8 + t * 2;
            *(float2*)(C + (size_t)r0 * N + c0) =
                make_float2(acc[mi][ni][0], acc[mi][ni][1]);
            *(float2*)(C + (size_t)(r0 + 8) * N + c0) =
                make_float2(acc[mi][ni][2], acc[mi][ni][3]);
        }
    }
}

// ---------------- RoPE + layout transforms ----------------------------------
__global__ void rope_q_kernel(const float* __restrict__ qp, const float* __restrict__ fc,
                              const float* __restrict__ fs, float* __restrict__ Qo) {
    int idx = blockIdx.x * blockDim.x + threadIdx.x;
    if (idx >= BATCH * SEQ * NH * HALF) return;
    int p = idx & 31;
    int h = (idx >> 5) & 31;
    int s = (idx >> 10) & 2047;
    int b = idx >> 21;
    const float* src = qp + (size_t)(b * SEQ + s) * HID + h * HD + 2 * p;
    float tr = src[0], ti = src[1];
    float c = fc[s * HALF + p], sn = fs[s * HALF + p];
    float* dst = Qo + ((size_t)(b * NH + h) * SEQ + s) * HD + 2 * p;
    dst[0] = (tr * c - ti * sn) * 0.125f;   // fold 1/sqrt(64)
    dst[1] = (tr * sn + ti * c) * 0.125f;
}

__global__ void rope_k_kernel(const float* __restrict__ kp, const float* __restrict__ fc,
                              const float* __restrict__ fs, float* __restrict__ Ko) {
    int idx = blockIdx.x * blockDim.x + threadIdx.x;
    if (idx >= BATCH * SEQ * NKV * HALF) return;
    int p = idx & 31;
    int kvh = (idx >> 5) & 7;
    int s = (idx >> 8) & 2047;
    int b = idx >> 19;
    const float* src = kp + (size_t)(b * SEQ + s) * (NKV * HD) + kvh * HD + 2 * p;
    float tr = src[0], ti = src[1];
    float c = fc[s * HALF + p], sn = fs[s * HALF + p];
    float* dst = Ko + ((size_t)(b * NKV + kvh) * SEQ + s) * HD + 2 * p;
    dst[0] = tr * c - ti * sn;
    dst[1] = tr * sn + ti * c;
}

__global__ void copy_v_kernel(const float* __restrict__ vp, float* __restrict__ Vo) {
    int idx = blockIdx.x * blockDim.x + threadIdx.x;
    if (idx >= BATCH * SEQ * NKV * HD) return;
    int d = idx & 63;
    int kvh = (idx >> 6) & 7;
    int s = (idx >> 9) & 2047;
    int b = idx >> 20;
    Vo[((size_t)(b * NKV + kvh) * SEQ + s) * HD + d] =
        vp[(size_t)(b * SEQ + s) * (NKV * HD) + kvh * HD + d];
}

// ---------------- tensor-core flash attention (tf32 mma.sync) ----------------
// CTA: 128 q-rows x one (b,h). 8 warps, warp w owns q-rows w*16..w*16+15.
// K-tile = 64 keys. Smem: Qs[128][68] tf32, Ks[64][68], Vs[64][72], Ps[8][16][68].
#define QPITCH 68
#define KPITCH 68
#define VPITCH 72
#define SM_QS 0
#define SM_KS (128 * QPITCH)
#define SM_VS (SM_KS + 64 * KPITCH)
#define SM_PS (SM_VS + 64 * VPITCH)
#define ATTN_SMEM_W (SM_PS + 8 * 16 * QPITCH)
#define ATTN_SMEM (ATTN_SMEM_W * 4)

__global__ __launch_bounds__(256)
void attn_tc_kernel(const float* __restrict__ Q, const float* __restrict__ K,
                    const float* __restrict__ V, float* __restrict__ O) {
    extern __shared__ uint32_t sm[];
    uint32_t* Qs = sm + SM_QS;
    uint32_t* Ks = sm + SM_KS;
    uint32_t* Vs = sm + SM_VS;
    uint32_t* Ps = sm + SM_PS;

    int tid = threadIdx.x;
    int w = tid >> 5, lane = tid & 31;
    int g = lane >> 2, t = lane & 3;
    int qt = blockIdx.x, bh = blockIdx.y;
    int b = bh >> 5, h = bh & 31;
    int kvh = h >> 2;
    int q0 = qt * 128;
    int qrow = w * 16;

    const float* Qb = Q + ((size_t)(b * NH + h) * SEQ + q0) * HD;
    const float* Kb = K + (size_t)(b * NKV + kvh) * SEQ * HD;
    const float* Vb = V + (size_t)(b * NKV + kvh) * SEQ * HD;

    // load Q tile (128x64) -> tf32 smem
#pragma unroll
    for (int p = 0; p < 8; p++) {
        int idx = p * 256 + tid;
        int row = idx >> 4, c4 = (idx & 15) << 2;
        float4 qv = *(const float4*)(Qb + (size_t)row * HD + c4);
        uint32_t* qp_ = Qs + row * QPITCH + c4;
        qp_[0] = f2tf(qv.x); qp_[1] = f2tf(qv.y);
        qp_[2] = f2tf(qv.z); qp_[3] = f2tf(qv.w);
    }

    float oacc[8][4];
#pragma unroll
    for (int ni = 0; ni < 8; ni++)
#pragma unroll
        for (int e = 0; e < 4; e++) oacc[ni][e] = 0.0f;
    float m0 = -1e30f, m1 = -1e30f, l0 = 0.0f, l1 = 0.0f;

    int ktmax = (q0 >> 6) + 1;
    for (int kt = 0; kt <= ktmax; kt++) {
        const float* Kp = Kb + (size_t)kt * 64 * HD;
        const float* Vp = Vb + (size_t)kt * 64 * HD;
        __syncthreads();   // Ks/Vs free (also orders Qs on first iter)
#pragma unroll
        for (int p = 0; p < 4; p++) {
            int idx = p * 256 + tid;
            int row = idx >> 4, c4 = (idx & 15) << 2;
            float4 kv = *(const float4*)(Kp + (size_t)row * HD + c4);
            uint32_t* kp_ = Ks + row * KPITCH + c4;
            kp_[0] = f2tf(kv.x); kp_[1] = f2tf(kv.y);
            kp_[2] = f2tf(kv.z); kp_[3] = f2tf(kv.w);
            float4 vv = *(const float4*)(Vp + (size_t)row * HD + c4);
            uint32_t* vp_ = Vs + row * VPITCH + c4;
            vp_[0] = f2tf(vv.x); vp_[1] = f2tf(vv.y);
            vp_[2] = f2tf(vv.z); vp_[3] = f2tf(vv.w);
        }
        __syncthreads();

        // ---- S = Q K^T  (warp rows qrow..qrow+15, cols 0..63 of tile) ----
        float sa[8][4];
#pragma unroll
        for (int ni = 0; ni < 8; ni++)
#pragma unroll
            for (int e = 0; e < 4; e++) sa[ni][e] = 0.0f;
#pragma unroll
        for (int ks = 0; ks < 8; ks++) {
            int kk = ks * 8;
            uint32_t a[4];
            a[0] = Qs[(qrow + g) * QPITCH + kk + t];
            a[1] = Qs[(qrow + 8 + g) * QPITCH + kk + t];
            a[2] = Qs[(qrow + g) * QPITCH + kk + t + 4];
            a[3] = Qs[(qrow + 8 + g) * QPITCH + kk + t + 4];
#pragma unroll
            for (int ni = 0; ni < 8; ni++) {
                uint32_t bfr[2];
                bfr[0] = Ks[(ni * 8 + g) * KPITCH + kk + t];
                bfr[1] = Ks[(ni * 8 + g) * KPITCH + kk + t + 4];
                MMA_TF32(sa[ni], a, bfr);
            }
        }

        // ---- causal mask (only near diagonal) ----
        int r0 = q0 + qrow + g, r1 = r0 + 8;
        if (kt * 64 + 63 > r0) {
            int cb = kt * 64;
#pragma unroll
            for (int ni = 0; ni < 8; ni++) {
                int c0 = cb + ni * 8 + 2 * t, c1 = c0 + 1;
                if (c0 > r0) sa[ni][0] = -1e30f;
                if (c1 > r0) sa[ni][1] = -1e30f;
                if (c0 > r1) sa[ni][2] = -1e30f;
                if (c1 > r1) sa[ni][3] = -1e30f;
            }
        }

        // ---- online softmax (rows owned by 4 t-lanes of quad g) ----
        float mx0 = -1e30f, mx1 = -1e30f;
#pragma unroll
        for (int ni = 0; ni < 8; ni++) {
            mx0 = fmaxf(mx0, fmaxf(sa[ni][0], sa[ni][1]));
            mx1 = fmaxf(mx1, fmaxf(sa[ni][2], sa[ni][3]));
        }
        mx0 = fmaxf(mx0, __shfl_xor_sync(0xffffffffu, mx0, 1));
        mx0 = fmaxf(mx0, __shfl_xor_sync(0xffffffffu, mx0, 2));
        mx1 = fmaxf(mx1, __shfl_xor_sync(0xffffffffu, mx1, 1));
        mx1 = fmaxf(mx1, __shfl_xor_sync(0xffffffffu, mx1, 2));
        float mn0 = fmaxf(m0, mx0), mn1 = fmaxf(m1, mx1);
        float sc0 = __expf(m0 - mn0), sc1 = __expf(m1 - mn1);
        m0 = mn0; m1 = mn1;
        float sum0 = 0.0f, sum1 = 0.0f;
#pragma unroll
        for (int ni = 0; ni < 8; ni++) {
            sa[ni][0] = __expf(sa[ni][0] - mn0); sum0 += sa[ni][0];
            sa[ni][1] = __expf(sa[ni][1] - mn0); sum0 += sa[ni][1];
            sa[ni][2] = __expf(sa[ni][2] - mn1); sum1 += sa[ni][2];
            sa[ni][3] = __expf(sa[ni][3] - mn1); sum1 += sa[ni][3];
        }
        sum0 += __shfl_xor_sync(0xffffffffu, sum0, 1);
        sum0 += __shfl_xor_sync(0xffffffffu, sum0, 2);
        sum1 += __shfl_xor_sync(0xffffffffu, sum1, 1);
        sum1 += __shfl_xor_sync(0xffffffffu, sum1, 2);
        l0 = l0 * sc0 + sum0;
        l1 = l1 * sc1 + sum1;
#pragma unroll
        for (int ni = 0; ni < 8; ni++) {
            oacc[ni][0] *= sc0; oacc[ni][1] *= sc0;
            oacc[ni][2] *= sc1; oacc[ni][3] *= sc1;
        }

        // ---- P -> smem (tf32), per-warp region ----
        uint32_t* Pw = Ps + w * 16 * QPITCH;
#pragma unroll
        for (int ni = 0; ni < 8; ni++) {
            int c = ni * 8 + 2 * t;
            Pw[g * QPITCH + c]     = f2tf(sa[ni][0]);
            Pw[g * QPITCH + c + 1] = f2tf(sa[ni][1]);
            Pw[(g + 8) * QPITCH + c]     = f2tf(sa[ni][2]);
            Pw[(g + 8) * QPITCH + c + 1] = f2tf(sa[ni][3]);
        }
        __syncwarp();

        // ---- O += P V ----
#pragma unroll
        for (int ks = 0; ks < 8; ks++) {
            int kk = ks * 8;
            uint32_t a[4];
            a[0] = Pw[g * QPITCH + kk + t];
            a[1] = Pw[(g + 8) * QPITCH + kk + t];
            a[2] = Pw[g * QPITCH + kk + t + 4];
            a[3] = Pw[(g + 8) * QPITCH + kk + t + 4];
#pragma unroll
            for (int ni = 0; ni < 8; ni++) {
                uint32_t bfr[2];
                bfr[0] = Vs[(kk + t) * VPITCH + ni * 8 + g];
                bfr[1] = Vs[(kk + t + 4) * VPITCH + ni * 8 + g];
                MMA_TF32(oacc[ni], a, bfr);
            }
        }
        __syncwarp();
    }

    // ---- normalize + write [B,S,H,D] ----
    float rl0 = 1.0f / l0, rl1 = 1.0f / l1;
    int r0 = q0 + qrow + g, r1 = r0 + 8;
#pragma unroll
    for (int ni = 0; ni < 8; ni++) {
        int col = ni * 8 + 2 * t;
        *(float2*)(O + ((size_t)(b * SEQ + r0) * NH + h) * HD + col) =
            make_float2(oacc[ni][0] * rl0, oacc[ni][1] * rl0);
        *(float2*)(O + ((size_t)(b * SEQ + r1) * NH + h) * HD + col) =
            make_float2(oacc[ni][2] * rl1, oacc[ni][3] * rl1);
    }
}

// ---------------- launcher ---------------------------------------------------
extern "C" void kernel_launch(void* const* d_in, const int* in_sizes, int n_in,
                              void* d_out, int out_size) {
    const float* x  = (const float*)d_in[0];
    const float* wq = (const float*)d_in[1];
    const float* wk = (const float*)d_in[2];
    const float* wv = (const float*)d_in[3];
    const float* wo = (const float*)d_in[4];
    const float* fc = (const float*)d_in[5];
    const float* fs = (const float*)d_in[6];
    float* out = (float*)d_out;

    float *qp, *kp, *vp, *q, *k, *v, *ao, *wqT, *wkT, *wvT, *woT;
    cudaGetSymbolAddress((void**)&qp, g_qp);
    cudaGetSymbolAddress((void**)&kp, g_kp);
    cudaGetSymbolAddress((void**)&vp, g_vp);
    cudaGetSymbolAddress((void**)&q,  g_q);
    cudaGetSymbolAddress((void**)&k,  g_k);
    cudaGetSymbolAddress((void**)&v,  g_v);
    cudaGetSymbolAddress((void**)&ao, g_ao);
    cudaGetSymbolAddress((void**)&wqT, g_wqT);
    cudaGetSymbolAddress((void**)&wkT, g_wkT);
    cudaGetSymbolAddress((void**)&wvT, g_wvT);
    cudaGetSymbolAddress((void**)&woT, g_woT);

    const int M = BATCH * SEQ;  // 4096

    transpose_kernel<<<dim3(HID / 32, HID / 32), dim3(32, 8)>>>(wq, wqT, HID, HID);
    transpose_kernel<<<dim3((NKV * HD) / 32, HID / 32), dim3(32, 8)>>>(wk, wkT, HID, NKV * HD);
    transpose_kernel<<<dim3((NKV * HD) / 32, HID / 32), dim3(32, 8)>>>(wv, wvT, HID, NKV * HD);
    transpose_kernel<<<dim3(HID / 32, HID / 32), dim3(32, 8)>>>(wo, woT, HID, HID);

    cudaFuncSetAttribute(tf32_gemm, cudaFuncAttributeMaxDynamicSharedMemorySize,
                         GEMM_SMEM);

    tf32_gemm<<<dim3(HID / 128, M / 128), 256, GEMM_SMEM>>>(x, wqT, qp, HID);
    tf32_gemm<<<dim3((NKV * HD) / 128, M / 128), 256, GEMM_SMEM>>>(x, wkT, kp, NKV * HD);
    tf32_gemm<<<dim3((NKV * HD) / 128, M / 128), 256, GEMM_SMEM>>>(x, wvT, vp, NKV * HD);

    rope_q_kernel<<<(BATCH * SEQ * NH * HALF) / 256, 256>>>(qp, fc, fs, q);
    rope_k_kernel<<<(BATCH * SEQ * NKV * HALF) / 256, 256>>>(kp, fc, fs, k);
    copy_v_kernel<<<(BATCH * SEQ * NKV * HD) / 256, 256>>>(vp, v);

    cudaFuncSetAttribute(attn_tc_kernel, cudaFuncAttributeMaxDynamicSharedMemorySize,
                         ATTN_SMEM);
    attn_tc_kernel<<<dim3(SEQ / 128, BATCH * NH), 256, ATTN_SMEM>>>(q, k, v, ao);

    tf32_gemm<<<dim3(HID / 128, M / 128), 256, GEMM_SMEM>>>(ao, woT, out, HID);
}